// round 15
// baseline (speedup 1.0000x reference)
#include <cuda_runtime.h>
#include <cuda_bf16.h>
#include <stdint.h>
#include <math.h>

// ---------------------------------------------------------------------------
// B=4, N=1024, C=1024, H=16, HD=64
// All GEMM operands live as pre-split bf16 (hi, lo) pairs in global scratch.
// acc += Ah*Bh + Ah*Bl + Al*Bh  (fp32 accum; dropped lo*lo ~2^-16)
// NOTE: harness targets sm_100 (no 'a') — tcgen05 unavailable; mma.sync only.
// ---------------------------------------------------------------------------

#define M4 (1024 * 1024)

__device__ __nv_bfloat16 g_xh [4ULL * M4], g_xl [4ULL * M4];
__device__ __nv_bfloat16 g_w0h[1ULL * M4], g_w0l[1ULL * M4];
__device__ __nv_bfloat16 g_w1h[3ULL * M4], g_w1l[3ULL * M4];
__device__ __nv_bfloat16 g_p0h[1ULL * M4], g_p0l[1ULL * M4];
__device__ __nv_bfloat16 g_p1h[1ULL * M4], g_p1l[1ULL * M4];
__device__ __nv_bfloat16 g_t1h[4ULL * M4], g_t1l[4ULL * M4];
__device__ __nv_bfloat16 g_qh [12ULL * M4], g_ql [12ULL * M4];
__device__ __nv_bfloat16 g_ah [4ULL * M4], g_al [4ULL * M4];
__device__ __nv_bfloat16 g_t2h[4ULL * M4], g_t2l[4ULL * M4];

#define LDMX4(r, p) asm volatile( \
    "ldmatrix.sync.aligned.m8n8.x4.shared.b16 {%0,%1,%2,%3}, [%4];" \
    : "=r"((r)[0]), "=r"((r)[1]), "=r"((r)[2]), "=r"((r)[3]) : "r"(p))
#define LDMX4T(r, p) asm volatile( \
    "ldmatrix.sync.aligned.m8n8.x4.trans.shared.b16 {%0,%1,%2,%3}, [%4];" \
    : "=r"((r)[0]), "=r"((r)[1]), "=r"((r)[2]), "=r"((r)[3]) : "r"(p))
#define LDMX2(r, p) asm volatile( \
    "ldmatrix.sync.aligned.m8n8.x2.shared.b16 {%0,%1}, [%2];" \
    : "=r"((r)[0]), "=r"((r)[1]) : "r"(p))
#define LDMX2T(r, p) asm volatile( \
    "ldmatrix.sync.aligned.m8n8.x2.trans.shared.b16 {%0,%1}, [%2];" \
    : "=r"((r)[0]), "=r"((r)[1]) : "r"(p))
#define MMA16816(d, a, b) asm volatile( \
    "mma.sync.aligned.m16n8k16.row.col.f32.bf16.bf16.f32 " \
    "{%0,%1,%2,%3}, {%4,%5,%6,%7}, {%8,%9}, {%0,%1,%2,%3};" \
    : "+f"((d)[0]), "+f"((d)[1]), "+f"((d)[2]), "+f"((d)[3]) \
    : "r"((a)[0]), "r"((a)[1]), "r"((a)[2]), "r"((a)[3]), \
      "r"((b)[0]), "r"((b)[1]))
#define CP_COMMIT() asm volatile("cp.async.commit_group;")
#define CP_WAIT(n)  asm volatile("cp.async.wait_group %0;" :: "n"(n))

__device__ __forceinline__ uint32_t cvta_s(const void* p) {
    return (uint32_t)__cvta_generic_to_shared(p);
}
__device__ __forceinline__ void cpa16(uint32_t dst, const void* src) {
    asm volatile("cp.async.ca.shared.global [%0], [%1], 16;" :: "r"(dst), "l"(src));
}
__device__ __forceinline__ void split_bf16(float v, __nv_bfloat16& hi, __nv_bfloat16& lo) {
    hi = __float2bfloat16(v);
    lo = __float2bfloat16(v - __bfloat162float(hi));
}
__device__ __forceinline__ uint32_t pack_bf2(float a, float b) {
    __nv_bfloat162 t = __floats2bfloat162_rn(a, b);
    return *(uint32_t*)&t;
}

// ---------------------------------------------------------------------------
// Merged pre-split: one launch covers x, Wq0, Wq1, Wp0, Wp1 (range dispatch)
// ---------------------------------------------------------------------------
__global__ __launch_bounds__(256)
void presplit5(const float4* __restrict__ x,  const float4* __restrict__ w0,
               const float4* __restrict__ w1, const float4* __restrict__ p0,
               const float4* __restrict__ p1,
               __nv_bfloat162* __restrict__ xh,  __nv_bfloat162* __restrict__ xl,
               __nv_bfloat162* __restrict__ w0h, __nv_bfloat162* __restrict__ w0l,
               __nv_bfloat162* __restrict__ w1h, __nv_bfloat162* __restrict__ w1l,
               __nv_bfloat162* __restrict__ p0h, __nv_bfloat162* __restrict__ p0l,
               __nv_bfloat162* __restrict__ p1h, __nv_bfloat162* __restrict__ p1l)
{
    long i = (long)blockIdx.x * 256 + threadIdx.x;
    const float4* in; __nv_bfloat162 *oh, *ol; long j;
    if      (i < 1048576) { in = x;  j = i;           oh = xh;  ol = xl;  }
    else if (i < 1310720) { in = w0; j = i - 1048576; oh = w0h; ol = w0l; }
    else if (i < 2097152) { in = w1; j = i - 1310720; oh = w1h; ol = w1l; }
    else if (i < 2359296) { in = p0; j = i - 2097152; oh = p0h; ol = p0l; }
    else                  { in = p1; j = i - 2359296; oh = p1h; ol = p1l; }

    float4 v = in[j];
    float f[4] = {v.x, v.y, v.z, v.w};
    __nv_bfloat16 hh[4], ll[4];
    #pragma unroll
    for (int e = 0; e < 4; e++) split_bf16(f[e], hh[e], ll[e]);
    oh[2 * j]     = __halves2bfloat162(hh[0], hh[1]);
    oh[2 * j + 1] = __halves2bfloat162(hh[2], hh[3]);
    ol[2 * j]     = __halves2bfloat162(ll[0], ll[1]);
    ol[2 * j + 1] = __halves2bfloat162(ll[2], ll[3]);
}

// ---------------------------------------------------------------------------
// bf16x3 tensor-core GEMM, 128x128x32 tile, 2-stage (R13 proven version).
// ---------------------------------------------------------------------------
template<bool BT, bool BIAS_COL, bool SPLIT_OUT>
__global__ __launch_bounds__(256, 2)
void bgemm(const __nv_bfloat16* __restrict__ Ah, const __nv_bfloat16* __restrict__ Al,
           const __nv_bfloat16* __restrict__ Bh, const __nv_bfloat16* __restrict__ Bl,
           const float* __restrict__ bias, float* __restrict__ C,
           __nv_bfloat16* __restrict__ Ch, __nv_bfloat16* __restrict__ Cl,
           int M, int N, int K, long sA, long sB, long sC)
{
    Ah += (long)blockIdx.z * sA;  Al += (long)blockIdx.z * sA;
    Bh += (long)blockIdx.z * sB;  Bl += (long)blockIdx.z * sB;
    if (SPLIT_OUT) { Ch += (long)blockIdx.z * sC; Cl += (long)blockIdx.z * sC; }
    else           { C  += (long)blockIdx.z * sC; }

    constexpr int A_STR = 40;
    constexpr int B_STR = BT ? 40 : 136;
    constexpr int ASZ = 128 * A_STR;
    constexpr int BSZ = BT ? 128 * B_STR : 32 * B_STR;
    constexpr int STG = 2 * ASZ + 2 * BSZ;

    extern __shared__ __align__(16) __nv_bfloat16 sm[];

    const int tid  = threadIdx.x;
    const int lane = tid & 31;
    const int warp = tid >> 5;
    const int wm = (warp & 1) * 64;
    const int wn = (warp >> 1) * 32;
    const int m0 = blockIdx.y * 128;
    const int n0 = blockIdx.x * 128;

    const int r  = tid >> 1;
    const int kc = (tid & 1) * 2;
    const int rb = tid >> 3;
    const int cc = (tid & 7) * 2;

    auto issue = [&](int k0, int st) {
        __nv_bfloat16* base = sm + st * STG;
        const __nv_bfloat16* gA  = Ah + (long)(m0 + r) * K + k0 + kc * 8;
        const __nv_bfloat16* gAl = Al + (long)(m0 + r) * K + k0 + kc * 8;
        uint32_t dA  = cvta_s(base + r * A_STR + kc * 8);
        uint32_t dAl = cvta_s(base + ASZ + r * A_STR + kc * 8);
        cpa16(dA, gA);        cpa16(dA + 16, gA + 8);
        cpa16(dAl, gAl);      cpa16(dAl + 16, gAl + 8);
        if (BT) {
            const __nv_bfloat16* gB  = Bh + (long)(n0 + r) * K + k0 + kc * 8;
            const __nv_bfloat16* gBl = Bl + (long)(n0 + r) * K + k0 + kc * 8;
            uint32_t dB  = cvta_s(base + 2 * ASZ + r * B_STR + kc * 8);
            uint32_t dBl = cvta_s(base + 2 * ASZ + BSZ + r * B_STR + kc * 8);
            cpa16(dB, gB);    cpa16(dB + 16, gB + 8);
            cpa16(dBl, gBl);  cpa16(dBl + 16, gBl + 8);
        } else {
            const __nv_bfloat16* gB  = Bh + (long)(k0 + rb) * N + n0 + cc * 8;
            const __nv_bfloat16* gBl = Bl + (long)(k0 + rb) * N + n0 + cc * 8;
            uint32_t dB  = cvta_s(base + 2 * ASZ + rb * B_STR + cc * 8);
            uint32_t dBl = cvta_s(base + 2 * ASZ + BSZ + rb * B_STR + cc * 8);
            cpa16(dB, gB);    cpa16(dB + 16, gB + 8);
            cpa16(dBl, gBl);  cpa16(dBl + 16, gBl + 8);
        }
    };

    float acc[4][4][4];
    #pragma unroll
    for (int i = 0; i < 4; i++)
        #pragma unroll
        for (int j = 0; j < 4; j++)
            #pragma unroll
            for (int e = 0; e < 4; e++) acc[i][j][e] = 0.f;

    issue(0, 0); CP_COMMIT();

    int cur = 0;
    for (int k0 = 0; k0 < K; k0 += 32) {
        const bool more = (k0 + 32) < K;
        if (more) { issue(k0 + 32, cur ^ 1); CP_COMMIT(); }
        if (more) CP_WAIT(1); else CP_WAIT(0);
        __syncthreads();

        const __nv_bfloat16* aH = sm + cur * STG;
        const __nv_bfloat16* aL = aH + ASZ;
        const __nv_bfloat16* bH = aH + 2 * ASZ;
        const __nv_bfloat16* bL = bH + BSZ;

        #pragma unroll
        for (int ks = 0; ks < 2; ks++) {
            const int kk = ks * 16;
            uint32_t ah[4][4], al[4][4];
            #pragma unroll
            for (int fm = 0; fm < 4; fm++) {
                const int row = wm + fm * 16 + (lane & 15);
                const int col = kk + (lane >> 4) * 8;
                LDMX4(ah[fm], cvta_s(aH + row * A_STR + col));
                LDMX4(al[fm], cvta_s(aL + row * A_STR + col));
            }
            uint32_t bh4[2][4], bl4[2][4];
            #pragma unroll
            for (int fp = 0; fp < 2; fp++) {
                const int fn = fp * 2;
                if (BT) {
                    const int row = wn + fn * 8 + (lane & 7) + ((lane >> 4) * 8);
                    const int col = kk + ((lane >> 3) & 1) * 8;
                    LDMX4(bh4[fp], cvta_s(bH + row * B_STR + col));
                    LDMX4(bl4[fp], cvta_s(bL + row * B_STR + col));
                } else {
                    const int row = kk + (lane & 7) + (((lane >> 3) & 1) * 8);
                    const int col = wn + fn * 8 + ((lane >> 4) * 8);
                    LDMX4T(bh4[fp], cvta_s(bH + row * B_STR + col));
                    LDMX4T(bl4[fp], cvta_s(bL + row * B_STR + col));
                }
            }
            #pragma unroll
            for (int fn = 0; fn < 4; fn++) {
                const int fp = fn >> 1, hf = (fn & 1) * 2;
                uint32_t bh2[2] = { bh4[fp][hf], bh4[fp][hf + 1] };
                uint32_t bl2[2] = { bl4[fp][hf], bl4[fp][hf + 1] };
                #pragma unroll
                for (int fm = 0; fm < 4; fm++) {
                    MMA16816(acc[fm][fn], ah[fm], bh2);
                    MMA16816(acc[fm][fn], ah[fm], bl2);
                    MMA16816(acc[fm][fn], al[fm], bh2);
                }
            }
        }
        __syncthreads();
        cur ^= 1;
    }

    #pragma unroll
    for (int fm = 0; fm < 4; fm++) {
        #pragma unroll
        for (int fn = 0; fn < 4; fn++) {
            const int row = m0 + wm + fm * 16 + (lane >> 2);
            const int col = n0 + wn + fn * 8 + (lane & 3) * 2;
            float b0, b1, b0b, b1b;
            if (BIAS_COL) { b0 = bias[col]; b1 = bias[col + 1]; b0b = b0; b1b = b1; }
            else          { b0 = bias[row]; b1 = b0; b0b = bias[row + 8]; b1b = b0b; }
            float v0 = acc[fm][fn][0] + b0,  v1 = acc[fm][fn][1] + b1;
            float v2 = acc[fm][fn][2] + b0b, v3 = acc[fm][fn][3] + b1b;
            if (SPLIT_OUT) {
                __nv_bfloat16 h0, l0, h1, l1;
                split_bf16(v0, h0, l0); split_bf16(v1, h1, l1);
                *(__nv_bfloat162*)(Ch + (long)row * N + col) = __halves2bfloat162(h0, h1);
                *(__nv_bfloat162*)(Cl + (long)row * N + col) = __halves2bfloat162(l0, l1);
                split_bf16(v2, h0, l0); split_bf16(v3, h1, l1);
                *(__nv_bfloat162*)(Ch + (long)(row + 8) * N + col) = __halves2bfloat162(h0, h1);
                *(__nv_bfloat162*)(Cl + (long)(row + 8) * N + col) = __halves2bfloat162(l0, l1);
            } else {
                *(float2*)(C + (long)row * N + col)       = make_float2(v0, v1);
                *(float2*)(C + (long)(row + 8) * N + col) = make_float2(v2, v3);
            }
        }
    }
}

// ---------------------------------------------------------------------------
// bf16x3 BT GEMM, 128x256x32 tile, 8 warps at 64x64, 2-stage, split output.
// Higher MMA:ldmatrix ratio (6:1 vs 4:1) and half the barriers per output.
// Used for the qkv channel-linear (M=4096, N=3072, K=1024).
// ---------------------------------------------------------------------------
__global__ __launch_bounds__(256, 1)
void bgemm_bt256(const __nv_bfloat16* __restrict__ Ah, const __nv_bfloat16* __restrict__ Al,
                 const __nv_bfloat16* __restrict__ Bh, const __nv_bfloat16* __restrict__ Bl,
                 const float* __restrict__ bias,
                 __nv_bfloat16* __restrict__ Ch, __nv_bfloat16* __restrict__ Cl,
                 int M, int N, int K)
{
    constexpr int A_STR = 40;
    constexpr int B_STR = 40;
    constexpr int ASZ = 128 * A_STR;          // 5120 halves
    constexpr int BSZ = 256 * B_STR;          // 10240 halves
    constexpr int STG = 2 * ASZ + 2 * BSZ;    // 30720 halves = 61440 B

    extern __shared__ __align__(16) __nv_bfloat16 sm[];

    const int tid  = threadIdx.x;
    const int lane = tid & 31;
    const int warp = tid >> 5;
    const int wm = (warp & 1) * 64;
    const int wn = (warp >> 1) * 64;          // 4 warps cover 256 cols
    const int m0 = blockIdx.y * 128;
    const int n0 = blockIdx.x * 256;

    const int r  = tid >> 1;                  // A row
    const int kc = (tid & 1) * 2;             // A chunk pair

    auto issue = [&](int k0, int st) {
        __nv_bfloat16* base = sm + st * STG;
        const __nv_bfloat16* gA  = Ah + (long)(m0 + r) * K + k0 + kc * 8;
        const __nv_bfloat16* gAl = Al + (long)(m0 + r) * K + k0 + kc * 8;
        uint32_t dA  = cvta_s(base + r * A_STR + kc * 8);
        uint32_t dAl = cvta_s(base + ASZ + r * A_STR + kc * 8);
        cpa16(dA, gA);        cpa16(dA + 16, gA + 8);
        cpa16(dAl, gAl);      cpa16(dAl + 16, gAl + 8);
        // B: one thread per row (256 rows), 4 chunks of 16B each
        const __nv_bfloat16* gB  = Bh + (long)(n0 + tid) * K + k0;
        const __nv_bfloat16* gBl = Bl + (long)(n0 + tid) * K + k0;
        uint32_t dB  = cvta_s(base + 2 * ASZ + tid * B_STR);
        uint32_t dBl = cvta_s(base + 2 * ASZ + BSZ + tid * B_STR);
        #pragma unroll
        for (int c = 0; c < 4; c++) {
            cpa16(dB  + c * 16, gB  + c * 8);
            cpa16(dBl + c * 16, gBl + c * 8);
        }
    };

    float acc[4][8][4];
    #pragma unroll
    for (int i = 0; i < 4; i++)
        #pragma unroll
        for (int j = 0; j < 8; j++)
            #pragma unroll
            for (int e = 0; e < 4; e++) acc[i][j][e] = 0.f;

    issue(0, 0); CP_COMMIT();

    int cur = 0;
    for (int k0 = 0; k0 < K; k0 += 32) {
        const bool more = (k0 + 32) < K;
        if (more) { issue(k0 + 32, cur ^ 1); CP_COMMIT(); }
        if (more) CP_WAIT(1); else CP_WAIT(0);
        __syncthreads();

        const __nv_bfloat16* aH = sm + cur * STG;
        const __nv_bfloat16* aL = aH + ASZ;
        const __nv_bfloat16* bH = aH + 2 * ASZ;
        const __nv_bfloat16* bL = bH + BSZ;

        #pragma unroll
        for (int ks = 0; ks < 2; ks++) {
            const int kk = ks * 16;
            uint32_t ah[4][4], al[4][4];
            #pragma unroll
            for (int fm = 0; fm < 4; fm++) {
                const int row = wm + fm * 16 + (lane & 15);
                const int col = kk + (lane >> 4) * 8;
                LDMX4(ah[fm], cvta_s(aH + row * A_STR + col));
                LDMX4(al[fm], cvta_s(aL + row * A_STR + col));
            }
            uint32_t bh4[4][4], bl4[4][4];
            #pragma unroll
            for (int fp = 0; fp < 4; fp++) {
                const int fn = fp * 2;
                const int row = wn + fn * 8 + (lane & 7) + ((lane >> 4) * 8);
                const int col = kk + ((lane >> 3) & 1) * 8;
                LDMX4(bh4[fp], cvta_s(bH + row * B_STR + col));
                LDMX4(bl4[fp], cvta_s(bL + row * B_STR + col));
            }
            #pragma unroll
            for (int fn = 0; fn < 8; fn++) {
                const int fp = fn >> 1, hf = (fn & 1) * 2;
                uint32_t bh2[2] = { bh4[fp][hf], bh4[fp][hf + 1] };
                uint32_t bl2[2] = { bl4[fp][hf], bl4[fp][hf + 1] };
                #pragma unroll
                for (int fm = 0; fm < 4; fm++) {
                    MMA16816(acc[fm][fn], ah[fm], bh2);
                    MMA16816(acc[fm][fn], ah[fm], bl2);
                    MMA16816(acc[fm][fn], al[fm], bh2);
                }
            }
        }
        __syncthreads();
        cur ^= 1;
    }

    #pragma unroll
    for (int fm = 0; fm < 4; fm++) {
        #pragma unroll
        for (int fn = 0; fn < 8; fn++) {
            const int row = m0 + wm + fm * 16 + (lane >> 2);
            const int col = n0 + wn + fn * 8 + (lane & 3) * 2;
            const float b0 = bias[col], b1 = bias[col + 1];
            float v0 = acc[fm][fn][0] + b0, v1 = acc[fm][fn][1] + b1;
            float v2 = acc[fm][fn][2] + b0, v3 = acc[fm][fn][3] + b1;
            __nv_bfloat16 h0, l0, h1, l1;
            split_bf16(v0, h0, l0); split_bf16(v1, h1, l1);
            *(__nv_bfloat162*)(Ch + (long)row * N + col) = __halves2bfloat162(h0, h1);
            *(__nv_bfloat162*)(Cl + (long)row * N + col) = __halves2bfloat162(l0, l1);
            split_bf16(v2, h0, l0); split_bf16(v3, h1, l1);
            *(__nv_bfloat162*)(Ch + (long)(row + 8) * N + col) = __halves2bfloat162(h0, h1);
            *(__nv_bfloat162*)(Cl + (long)(row + 8) * N + col) = __halves2bfloat162(l0, l1);
        }
    }
}

// ---------------------------------------------------------------------------
// Tensor-core flash attention, 2-CTA/SM (R13 proven version, unchanged).
// ---------------------------------------------------------------------------
#define AT_STR 72
#define AT_QSZ (64 * AT_STR)

__global__ __launch_bounds__(128)
void attn_mma(const __nv_bfloat16* __restrict__ qh_g, const __nv_bfloat16* __restrict__ ql_g,
              __nv_bfloat16* __restrict__ oh, __nv_bfloat16* __restrict__ ol)
{
    extern __shared__ __align__(16) __nv_bfloat16 sm[];
    __nv_bfloat16* Qh = sm;
    __nv_bfloat16* Ql = sm + AT_QSZ;

    const int tid  = threadIdx.x;
    const int lane = tid & 31;
    const int warp = tid >> 5;
    const int qc = blockIdx.x;
    const int h  = blockIdx.y;
    const int b  = blockIdx.z;
    const int n0 = qc * 64;

    const long boff = (long)b * 1024 * 3072 + h * 64;

    auto issueKV = [&](int kt, int st) {
        __nv_bfloat16* base = sm + 2 * AT_QSZ + st * 4 * AT_QSZ;
        const int k0 = kt * 64;
        #pragma unroll
        for (int j = 0; j < 4; j++) {
            const int idx = j * 128 + tid;
            const int rr = idx >> 3;
            const int c8 = (idx & 7) * 8;
            const long grow = boff + (long)(k0 + rr) * 3072;
            const int soff = rr * AT_STR + c8;
            cpa16(cvta_s(base + soff),               qh_g + grow + 1024 + c8);
            cpa16(cvta_s(base + AT_QSZ + soff),      ql_g + grow + 1024 + c8);
            cpa16(cvta_s(base + 2 * AT_QSZ + soff),  qh_g + grow + 2048 + c8);
            cpa16(cvta_s(base + 3 * AT_QSZ + soff),  ql_g + grow + 2048 + c8);
        }
    };

    issueKV(0, 0); CP_COMMIT();

    {
        const __nv_bfloat162 s2 = __floats2bfloat162_rn(0.125f, 0.125f);
        for (int idx = tid; idx < 512; idx += 128) {
            const int rr = idx >> 3;
            const int c8 = (idx & 7) * 8;
            const long grow = boff + (long)(n0 + rr) * 3072;
            uint4 vh = *(const uint4*)(qh_g + grow + c8);
            uint4 vl = *(const uint4*)(ql_g + grow + c8);
            __nv_bfloat162* ph = (__nv_bfloat162*)&vh;
            __nv_bfloat162* pl = (__nv_bfloat162*)&vl;
            #pragma unroll
            for (int e = 0; e < 4; e++) { ph[e] = __hmul2(ph[e], s2); pl[e] = __hmul2(pl[e], s2); }
            *(uint4*)(Qh + rr * AT_STR + c8) = vh;
            *(uint4*)(Ql + rr * AT_STR + c8) = vl;
        }
    }
    __syncthreads();

    uint32_t qh[4][4], ql[4][4];
    #pragma unroll
    for (int ks = 0; ks < 4; ks++) {
        const int row = warp * 16 + (lane & 15);
        const int col = ks * 16 + (lane >> 4) * 8;
        LDMX4(qh[ks], cvta_s(Qh + row * AT_STR + col));
        LDMX4(ql[ks], cvta_s(Ql + row * AT_STR + col));
    }

    float o[8][4];
    #pragma unroll
    for (int i = 0; i < 8; i++)
        #pragma unroll
        for (int e = 0; e < 4; e++) o[i][e] = 0.f;
    float mrow[2] = {-1e30f, -1e30f};
    float lrow[2] = {0.f, 0.f};

    int st = 0;
    for (int kt = 0; kt < 16; kt++) {
        const bool more = kt < 15;
        if (more) { issueKV(kt + 1, st ^ 1); CP_COMMIT(); }
        if (more) CP_WAIT(1); else CP_WAIT(0);
        __syncthreads();

        const __nv_bfloat16* Kh = sm + 2 * AT_QSZ + st * 4 * AT_QSZ;
        const __nv_bfloat16* Kl = Kh + AT_QSZ;
        const __nv_bfloat16* Vh = Kh + 2 * AT_QSZ;
        const __nv_bfloat16* Vl = Kh + 3 * AT_QSZ;

        float s[8][4];
        #pragma unroll
        for (int fn = 0; fn < 8; fn++)
            #pragma unroll
            for (int e = 0; e < 4; e++) s[fn][e] = 0.f;

        #pragma unroll
        for (int fn = 0; fn < 8; fn++) {
            #pragma unroll
            for (int ks = 0; ks < 4; ks++) {
                uint32_t kh2[2], kl2[2];
                const int row = fn * 8 + (lane & 7);
                const int col = ks * 16 + ((lane >> 3) & 1) * 8;
                LDMX2(kh2, cvta_s(Kh + row * AT_STR + col));
                LDMX2(kl2, cvta_s(Kl + row * AT_STR + col));
                MMA16816(s[fn], qh[ks], kh2);
                MMA16816(s[fn], qh[ks], kl2);
                MMA16816(s[fn], ql[ks], kh2);
            }
        }

        #pragma unroll
        for (int h2 = 0; h2 < 2; h2++) {
            float mx = mrow[h2];
            #pragma unroll
            for (int fn = 0; fn < 8; fn++)
                mx = fmaxf(mx, fmaxf(s[fn][2 * h2], s[fn][2 * h2 + 1]));
            mx = fmaxf(mx, __shfl_xor_sync(0xffffffffu, mx, 1));
            mx = fmaxf(mx, __shfl_xor_sync(0xffffffffu, mx, 2));
            const float alpha = __expf(mrow[h2] - mx);
            mrow[h2] = mx;
            float sum = 0.f;
            #pragma unroll
            for (int fn = 0; fn < 8; fn++) {
                float p0 = __expf(s[fn][2 * h2] - mx);
                float p1 = __expf(s[fn][2 * h2 + 1] - mx);
                s[fn][2 * h2] = p0; s[fn][2 * h2 + 1] = p1;
                sum += p0 + p1;
            }
            sum += __shfl_xor_sync(0xffffffffu, sum, 1);
            sum += __shfl_xor_sync(0xffffffffu, sum, 2);
            lrow[h2] = lrow[h2] * alpha + sum;
            #pragma unroll
            for (int fn = 0; fn < 8; fn++) {
                o[fn][2 * h2]     *= alpha;
                o[fn][2 * h2 + 1] *= alpha;
            }
        }

        uint32_t pk[4][4];
        #pragma unroll
        for (int kf = 0; kf < 4; kf++) {
            pk[kf][0] = pack_bf2(s[2 * kf][0],     s[2 * kf][1]);
            pk[kf][1] = pack_bf2(s[2 * kf][2],     s[2 * kf][3]);
            pk[kf][2] = pack_bf2(s[2 * kf + 1][0], s[2 * kf + 1][1]);
            pk[kf][3] = pack_bf2(s[2 * kf + 1][2], s[2 * kf + 1][3]);
        }

        #pragma unroll
        for (int kf = 0; kf < 4; kf++) {
            const int row = kf * 16 + (lane & 7) + ((lane >> 3) & 1) * 8;
            #pragma unroll
            for (int fn = 0; fn < 8; fn++) {
                uint32_t vh2[2], vl2[2];
                LDMX2T(vh2, cvta_s(Vh + row * AT_STR + fn * 8));
                LDMX2T(vl2, cvta_s(Vl + row * AT_STR + fn * 8));
                MMA16816(o[fn], pk[kf], vh2);
                MMA16816(o[fn], pk[kf], vl2);
            }
        }
        __syncthreads();
        st ^= 1;
    }

    const float inv0 = 1.f / lrow[0];
    const float inv1 = 1.f / lrow[1];
    const int r0 = n0 + warp * 16 + (lane >> 2);
    const int cb = h * 64 + (lane & 3) * 2;
    #pragma unroll
    for (int fn = 0; fn < 8; fn++) {
        const int col = cb + fn * 8;
        float v0 = o[fn][0] * inv0, v1 = o[fn][1] * inv0;
        float v2 = o[fn][2] * inv1, v3 = o[fn][3] * inv1;
        __nv_bfloat16 h0, l0, h1, l1;
        split_bf16(v0, h0, l0); split_bf16(v1, h1, l1);
        *(__nv_bfloat162*)(oh + ((long)b * 1024 + r0) * 1024 + col) = __halves2bfloat162(h0, h1);
        *(__nv_bfloat162*)(ol + ((long)b * 1024 + r0) * 1024 + col) = __halves2bfloat162(l0, l1);
        split_bf16(v2, h0, l0); split_bf16(v3, h1, l1);
        *(__nv_bfloat162*)(oh + ((long)b * 1024 + r0 + 8) * 1024 + col) = __halves2bfloat162(h0, h1);
        *(__nv_bfloat162*)(ol + ((long)b * 1024 + r0 + 8) * 1024 + col) = __halves2bfloat162(l0, l1);
    }
}

// ---------------------------------------------------------------------------
// Launch
// ---------------------------------------------------------------------------
extern "C" void kernel_launch(void* const* d_in, const int* in_sizes, int n_in,
                              void* d_out, int out_size)
{
    (void)in_sizes; (void)n_in; (void)out_size;
    const float* x   = (const float*)d_in[0];
    const float* Wq0 = (const float*)d_in[1];
    const float* bq0 = (const float*)d_in[2];
    const float* Wq1 = (const float*)d_in[3];
    const float* bq1 = (const float*)d_in[4];
    const float* Wp0 = (const float*)d_in[5];
    const float* bp0 = (const float*)d_in[6];
    const float* Wp1 = (const float*)d_in[7];
    const float* bp1 = (const float*)d_in[8];
    float* out = (float*)d_out;

    __nv_bfloat16 *xh, *xl, *w0h, *w0l, *w1h, *w1l, *p0h, *p0l, *p1h, *p1l;
    __nv_bfloat16 *t1h, *t1l, *qh, *ql, *ah, *al, *t2h, *t2l;
    cudaGetSymbolAddress((void**)&xh,  g_xh);  cudaGetSymbolAddress((void**)&xl,  g_xl);
    cudaGetSymbolAddress((void**)&w0h, g_w0h); cudaGetSymbolAddress((void**)&w0l, g_w0l);
    cudaGetSymbolAddress((void**)&w1h, g_w1h); cudaGetSymbolAddress((void**)&w1l, g_w1l);
    cudaGetSymbolAddress((void**)&p0h, g_p0h); cudaGetSymbolAddress((void**)&p0l, g_p0l);
    cudaGetSymbolAddress((void**)&p1h, g_p1h); cudaGetSymbolAddress((void**)&p1l, g_p1l);
    cudaGetSymbolAddress((void**)&t1h, g_t1h); cudaGetSymbolAddress((void**)&t1l, g_t1l);
    cudaGetSymbolAddress((void**)&qh,  g_qh);  cudaGetSymbolAddress((void**)&ql,  g_ql);
    cudaGetSymbolAddress((void**)&ah,  g_ah);  cudaGetSymbolAddress((void**)&al,  g_al);
    cudaGetSymbolAddress((void**)&t2h, g_t2h); cudaGetSymbolAddress((void**)&t2l, g_t2l);

    const int smem_bt   = 2 * ((2 * 128 * 40 + 2 * 128 * 40) * 2);  // 81920 B
    const int smem_nn   = 2 * ((2 * 128 * 40 + 2 * 32 * 136) * 2);  // 75776 B
    const int smem_bt256 = 2 * ((2 * 128 * 40 + 2 * 256 * 40) * 2); // 122880 B
    cudaFuncSetAttribute(bgemm<true, true, false>,
                         cudaFuncAttributeMaxDynamicSharedMemorySize, smem_bt);
    cudaFuncSetAttribute(bgemm<false, false, true>,
                         cudaFuncAttributeMaxDynamicSharedMemorySize, smem_nn);
    cudaFuncSetAttribute(bgemm_bt256,
                         cudaFuncAttributeMaxDynamicSharedMemorySize, smem_bt256);

    const int attn_smem = 10 * AT_QSZ * 2;                          // 92160 B
    cudaFuncSetAttribute(attn_mma,
                         cudaFuncAttributeMaxDynamicSharedMemorySize, attn_smem);

    dim3 blk(256);
    const long P = 1024L * 1024;

    // 0) merged pre-split (x + all four weights), one launch
    presplit5<<<10240, blk>>>((const float4*)x, (const float4*)Wq0, (const float4*)Wq1,
                              (const float4*)Wp0, (const float4*)Wp1,
                              (__nv_bfloat162*)xh,  (__nv_bfloat162*)xl,
                              (__nv_bfloat162*)w0h, (__nv_bfloat162*)w0l,
                              (__nv_bfloat162*)w1h, (__nv_bfloat162*)w1l,
                              (__nv_bfloat162*)p0h, (__nv_bfloat162*)p0l,
                              (__nv_bfloat162*)p1h, (__nv_bfloat162*)p1l);

    // 1) qkv seq-linear (NN, 2-stage): t1[b] = Wq0 @ x[b] + bq0
    bgemm<false, false, true><<<dim3(8, 8, 4), blk, smem_nn>>>(
        w0h, w0l, xh, xl, bq0, nullptr, t1h, t1l, 1024, 1024, 1024, 0, P, P);

    // 2) qkv channel-linear (BT, 128x256 tile): qkv = t1 @ Wq1^T + bq1
    bgemm_bt256<<<dim3(12, 32, 1), blk, smem_bt256>>>(
        t1h, t1l, w1h, w1l, bq1, qh, ql, 4096, 3072, 1024);

    // 3) flash attention (2 CTAs/SM, R13 version)
    attn_mma<<<dim3(16, 16, 4), dim3(128), attn_smem>>>(qh, ql, ah, al);

    // 4) proj seq-linear (NN, 2-stage)
    bgemm<false, false, true><<<dim3(8, 8, 4), blk, smem_nn>>>(
        p0h, p0l, ah, al, bp0, nullptr, t2h, t2l, 1024, 1024, 1024, 0, P, P);

    // 5) proj channel-linear (BT, 2-stage 128-tile) -> fp32 output
    bgemm<true, true, false><<<dim3(8, 32, 1), blk, smem_bt>>>(
        t2h, t2l, p1h, p1l, bp1, out, nullptr, nullptr, 4096, 1024, 1024, 0, 0, 0);
}

// round 17
// speedup vs baseline: 1.0806x; 1.0806x over previous
#include <cuda_runtime.h>
#include <cuda_bf16.h>
#include <stdint.h>
#include <math.h>

// ---------------------------------------------------------------------------
// B=4, N=1024, C=1024, H=16, HD=64
// All GEMM operands live as pre-split bf16 (hi, lo) pairs in global scratch.
// acc += Ah*Bh + Ah*Bl + Al*Bh  (fp32 accum; dropped lo*lo ~2^-16)
// NOTE: harness targets sm_100 (no 'a') — tcgen05 unavailable; mma.sync only.
// ---------------------------------------------------------------------------

#define M4 (1024 * 1024)

__device__ __nv_bfloat16 g_xh [4ULL * M4], g_xl [4ULL * M4];
__device__ __nv_bfloat16 g_w0h[1ULL * M4], g_w0l[1ULL * M4];
__device__ __nv_bfloat16 g_w1h[3ULL * M4], g_w1l[3ULL * M4];
__device__ __nv_bfloat16 g_p0h[1ULL * M4], g_p0l[1ULL * M4];
__device__ __nv_bfloat16 g_p1h[1ULL * M4], g_p1l[1ULL * M4];
__device__ __nv_bfloat16 g_t1h[4ULL * M4], g_t1l[4ULL * M4];
__device__ __nv_bfloat16 g_qh [12ULL * M4], g_ql [12ULL * M4];
__device__ __nv_bfloat16 g_ah [4ULL * M4], g_al [4ULL * M4];
__device__ __nv_bfloat16 g_t2h[4ULL * M4], g_t2l[4ULL * M4];

#define LDMX4(r, p) asm volatile( \
    "ldmatrix.sync.aligned.m8n8.x4.shared.b16 {%0,%1,%2,%3}, [%4];" \
    : "=r"((r)[0]), "=r"((r)[1]), "=r"((r)[2]), "=r"((r)[3]) : "r"(p))
#define LDMX4T(r, p) asm volatile( \
    "ldmatrix.sync.aligned.m8n8.x4.trans.shared.b16 {%0,%1,%2,%3}, [%4];" \
    : "=r"((r)[0]), "=r"((r)[1]), "=r"((r)[2]), "=r"((r)[3]) : "r"(p))
#define LDMX2(r, p) asm volatile( \
    "ldmatrix.sync.aligned.m8n8.x2.shared.b16 {%0,%1}, [%2];" \
    : "=r"((r)[0]), "=r"((r)[1]) : "r"(p))
#define LDMX2T(r, p) asm volatile( \
    "ldmatrix.sync.aligned.m8n8.x2.trans.shared.b16 {%0,%1}, [%2];" \
    : "=r"((r)[0]), "=r"((r)[1]) : "r"(p))
#define MMA16816(d, a, b) asm volatile( \
    "mma.sync.aligned.m16n8k16.row.col.f32.bf16.bf16.f32 " \
    "{%0,%1,%2,%3}, {%4,%5,%6,%7}, {%8,%9}, {%0,%1,%2,%3};" \
    : "+f"((d)[0]), "+f"((d)[1]), "+f"((d)[2]), "+f"((d)[3]) \
    : "r"((a)[0]), "r"((a)[1]), "r"((a)[2]), "r"((a)[3]), \
      "r"((b)[0]), "r"((b)[1]))
#define CP_COMMIT() asm volatile("cp.async.commit_group;")
#define CP_WAIT(n)  asm volatile("cp.async.wait_group %0;" :: "n"(n))

__device__ __forceinline__ uint32_t cvta_s(const void* p) {
    return (uint32_t)__cvta_generic_to_shared(p);
}
__device__ __forceinline__ void cpa16(uint32_t dst, const void* src) {
    asm volatile("cp.async.ca.shared.global [%0], [%1], 16;" :: "r"(dst), "l"(src));
}
__device__ __forceinline__ void split_bf16(float v, __nv_bfloat16& hi, __nv_bfloat16& lo) {
    hi = __float2bfloat16(v);
    lo = __float2bfloat16(v - __bfloat162float(hi));
}
__device__ __forceinline__ uint32_t pack_bf2(float a, float b) {
    __nv_bfloat162 t = __floats2bfloat162_rn(a, b);
    return *(uint32_t*)&t;
}

// ---------------------------------------------------------------------------
// Merged pre-split: one launch covers x, Wq0, Wq1, Wp0, Wp1 (range dispatch)
// ---------------------------------------------------------------------------
__global__ __launch_bounds__(256)
void presplit5(const float4* __restrict__ x,  const float4* __restrict__ w0,
               const float4* __restrict__ w1, const float4* __restrict__ p0,
               const float4* __restrict__ p1,
               __nv_bfloat162* __restrict__ xh,  __nv_bfloat162* __restrict__ xl,
               __nv_bfloat162* __restrict__ w0h, __nv_bfloat162* __restrict__ w0l,
               __nv_bfloat162* __restrict__ w1h, __nv_bfloat162* __restrict__ w1l,
               __nv_bfloat162* __restrict__ p0h, __nv_bfloat162* __restrict__ p0l,
               __nv_bfloat162* __restrict__ p1h, __nv_bfloat162* __restrict__ p1l)
{
    long i = (long)blockIdx.x * 256 + threadIdx.x;
    const float4* in; __nv_bfloat162 *oh, *ol; long j;
    if      (i < 1048576) { in = x;  j = i;           oh = xh;  ol = xl;  }
    else if (i < 1310720) { in = w0; j = i - 1048576; oh = w0h; ol = w0l; }
    else if (i < 2097152) { in = w1; j = i - 1310720; oh = w1h; ol = w1l; }
    else if (i < 2359296) { in = p0; j = i - 2097152; oh = p0h; ol = p0l; }
    else                  { in = p1; j = i - 2359296; oh = p1h; ol = p1l; }

    float4 v = in[j];
    float f[4] = {v.x, v.y, v.z, v.w};
    __nv_bfloat16 hh[4], ll[4];
    #pragma unroll
    for (int e = 0; e < 4; e++) split_bf16(f[e], hh[e], ll[e]);
    oh[2 * j]     = __halves2bfloat162(hh[0], hh[1]);
    oh[2 * j + 1] = __halves2bfloat162(hh[2], hh[3]);
    ol[2 * j]     = __halves2bfloat162(ll[0], ll[1]);
    ol[2 * j + 1] = __halves2bfloat162(ll[2], ll[3]);
}

// ---------------------------------------------------------------------------
// bf16x3 tensor-core GEMM, 128x128x32 tile, 2-stage (R13 proven version).
// ---------------------------------------------------------------------------
template<bool BT, bool BIAS_COL, bool SPLIT_OUT>
__global__ __launch_bounds__(256, 2)
void bgemm(const __nv_bfloat16* __restrict__ Ah, const __nv_bfloat16* __restrict__ Al,
           const __nv_bfloat16* __restrict__ Bh, const __nv_bfloat16* __restrict__ Bl,
           const float* __restrict__ bias, float* __restrict__ C,
           __nv_bfloat16* __restrict__ Ch, __nv_bfloat16* __restrict__ Cl,
           int M, int N, int K, long sA, long sB, long sC)
{
    Ah += (long)blockIdx.z * sA;  Al += (long)blockIdx.z * sA;
    Bh += (long)blockIdx.z * sB;  Bl += (long)blockIdx.z * sB;
    if (SPLIT_OUT) { Ch += (long)blockIdx.z * sC; Cl += (long)blockIdx.z * sC; }
    else           { C  += (long)blockIdx.z * sC; }

    constexpr int A_STR = 40;
    constexpr int B_STR = BT ? 40 : 136;
    constexpr int ASZ = 128 * A_STR;
    constexpr int BSZ = BT ? 128 * B_STR : 32 * B_STR;
    constexpr int STG = 2 * ASZ + 2 * BSZ;

    extern __shared__ __align__(16) __nv_bfloat16 sm[];

    const int tid  = threadIdx.x;
    const int lane = tid & 31;
    const int warp = tid >> 5;
    const int wm = (warp & 1) * 64;
    const int wn = (warp >> 1) * 32;
    const int m0 = blockIdx.y * 128;
    const int n0 = blockIdx.x * 128;

    const int r  = tid >> 1;
    const int kc = (tid & 1) * 2;
    const int rb = tid >> 3;
    const int cc = (tid & 7) * 2;

    auto issue = [&](int k0, int st) {
        __nv_bfloat16* base = sm + st * STG;
        const __nv_bfloat16* gA  = Ah + (long)(m0 + r) * K + k0 + kc * 8;
        const __nv_bfloat16* gAl = Al + (long)(m0 + r) * K + k0 + kc * 8;
        uint32_t dA  = cvta_s(base + r * A_STR + kc * 8);
        uint32_t dAl = cvta_s(base + ASZ + r * A_STR + kc * 8);
        cpa16(dA, gA);        cpa16(dA + 16, gA + 8);
        cpa16(dAl, gAl);      cpa16(dAl + 16, gAl + 8);
        if (BT) {
            const __nv_bfloat16* gB  = Bh + (long)(n0 + r) * K + k0 + kc * 8;
            const __nv_bfloat16* gBl = Bl + (long)(n0 + r) * K + k0 + kc * 8;
            uint32_t dB  = cvta_s(base + 2 * ASZ + r * B_STR + kc * 8);
            uint32_t dBl = cvta_s(base + 2 * ASZ + BSZ + r * B_STR + kc * 8);
            cpa16(dB, gB);    cpa16(dB + 16, gB + 8);
            cpa16(dBl, gBl);  cpa16(dBl + 16, gBl + 8);
        } else {
            const __nv_bfloat16* gB  = Bh + (long)(k0 + rb) * N + n0 + cc * 8;
            const __nv_bfloat16* gBl = Bl + (long)(k0 + rb) * N + n0 + cc * 8;
            uint32_t dB  = cvta_s(base + 2 * ASZ + rb * B_STR + cc * 8);
            uint32_t dBl = cvta_s(base + 2 * ASZ + BSZ + rb * B_STR + cc * 8);
            cpa16(dB, gB);    cpa16(dB + 16, gB + 8);
            cpa16(dBl, gBl);  cpa16(dBl + 16, gBl + 8);
        }
    };

    float acc[4][4][4];
    #pragma unroll
    for (int i = 0; i < 4; i++)
        #pragma unroll
        for (int j = 0; j < 4; j++)
            #pragma unroll
            for (int e = 0; e < 4; e++) acc[i][j][e] = 0.f;

    issue(0, 0); CP_COMMIT();

    int cur = 0;
    for (int k0 = 0; k0 < K; k0 += 32) {
        const bool more = (k0 + 32) < K;
        if (more) { issue(k0 + 32, cur ^ 1); CP_COMMIT(); }
        if (more) CP_WAIT(1); else CP_WAIT(0);
        __syncthreads();

        const __nv_bfloat16* aH = sm + cur * STG;
        const __nv_bfloat16* aL = aH + ASZ;
        const __nv_bfloat16* bH = aH + 2 * ASZ;
        const __nv_bfloat16* bL = bH + BSZ;

        #pragma unroll
        for (int ks = 0; ks < 2; ks++) {
            const int kk = ks * 16;
            uint32_t ah[4][4], al[4][4];
            #pragma unroll
            for (int fm = 0; fm < 4; fm++) {
                const int row = wm + fm * 16 + (lane & 15);
                const int col = kk + (lane >> 4) * 8;
                LDMX4(ah[fm], cvta_s(aH + row * A_STR + col));
                LDMX4(al[fm], cvta_s(aL + row * A_STR + col));
            }
            uint32_t bh4[2][4], bl4[2][4];
            #pragma unroll
            for (int fp = 0; fp < 2; fp++) {
                const int fn = fp * 2;
                if (BT) {
                    const int row = wn + fn * 8 + (lane & 7) + ((lane >> 4) * 8);
                    const int col = kk + ((lane >> 3) & 1) * 8;
                    LDMX4(bh4[fp], cvta_s(bH + row * B_STR + col));
                    LDMX4(bl4[fp], cvta_s(bL + row * B_STR + col));
                } else {
                    const int row = kk + (lane & 7) + (((lane >> 3) & 1) * 8);
                    const int col = wn + fn * 8 + ((lane >> 4) * 8);
                    LDMX4T(bh4[fp], cvta_s(bH + row * B_STR + col));
                    LDMX4T(bl4[fp], cvta_s(bL + row * B_STR + col));
                }
            }
            #pragma unroll
            for (int fn = 0; fn < 4; fn++) {
                const int fp = fn >> 1, hf = (fn & 1) * 2;
                uint32_t bh2[2] = { bh4[fp][hf], bh4[fp][hf + 1] };
                uint32_t bl2[2] = { bl4[fp][hf], bl4[fp][hf + 1] };
                #pragma unroll
                for (int fm = 0; fm < 4; fm++) {
                    MMA16816(acc[fm][fn], ah[fm], bh2);
                    MMA16816(acc[fm][fn], ah[fm], bl2);
                    MMA16816(acc[fm][fn], al[fm], bh2);
                }
            }
        }
        __syncthreads();
        cur ^= 1;
    }

    #pragma unroll
    for (int fm = 0; fm < 4; fm++) {
        #pragma unroll
        for (int fn = 0; fn < 4; fn++) {
            const int row = m0 + wm + fm * 16 + (lane >> 2);
            const int col = n0 + wn + fn * 8 + (lane & 3) * 2;
            float b0, b1, b0b, b1b;
            if (BIAS_COL) { b0 = bias[col]; b1 = bias[col + 1]; b0b = b0; b1b = b1; }
            else          { b0 = bias[row]; b1 = b0; b0b = bias[row + 8]; b1b = b0b; }
            float v0 = acc[fm][fn][0] + b0,  v1 = acc[fm][fn][1] + b1;
            float v2 = acc[fm][fn][2] + b0b, v3 = acc[fm][fn][3] + b1b;
            if (SPLIT_OUT) {
                __nv_bfloat16 h0, l0, h1, l1;
                split_bf16(v0, h0, l0); split_bf16(v1, h1, l1);
                *(__nv_bfloat162*)(Ch + (long)row * N + col) = __halves2bfloat162(h0, h1);
                *(__nv_bfloat162*)(Cl + (long)row * N + col) = __halves2bfloat162(l0, l1);
                split_bf16(v2, h0, l0); split_bf16(v3, h1, l1);
                *(__nv_bfloat162*)(Ch + (long)(row + 8) * N + col) = __halves2bfloat162(h0, h1);
                *(__nv_bfloat162*)(Cl + (long)(row + 8) * N + col) = __halves2bfloat162(l0, l1);
            } else {
                *(float2*)(C + (long)row * N + col)       = make_float2(v0, v1);
                *(float2*)(C + (long)(row + 8) * N + col) = make_float2(v2, v3);
            }
        }
    }
}

// ---------------------------------------------------------------------------
// Tensor-core flash attention, 2-CTA/SM (R13 shape) + x4 ldmatrix for K and V
// (proven mappings from bgemm's BT and NN-trans paths). Numerics identical.
// ---------------------------------------------------------------------------
#define AT_STR 72
#define AT_QSZ (64 * AT_STR)

__global__ __launch_bounds__(128)
void attn_mma(const __nv_bfloat16* __restrict__ qh_g, const __nv_bfloat16* __restrict__ ql_g,
              __nv_bfloat16* __restrict__ oh, __nv_bfloat16* __restrict__ ol)
{
    extern __shared__ __align__(16) __nv_bfloat16 sm[];
    __nv_bfloat16* Qh = sm;
    __nv_bfloat16* Ql = sm + AT_QSZ;

    const int tid  = threadIdx.x;
    const int lane = tid & 31;
    const int warp = tid >> 5;
    const int qc = blockIdx.x;
    const int h  = blockIdx.y;
    const int b  = blockIdx.z;
    const int n0 = qc * 64;

    const long boff = (long)b * 1024 * 3072 + h * 64;

    auto issueKV = [&](int kt, int st) {
        __nv_bfloat16* base = sm + 2 * AT_QSZ + st * 4 * AT_QSZ;
        const int k0 = kt * 64;
        #pragma unroll
        for (int j = 0; j < 4; j++) {
            const int idx = j * 128 + tid;
            const int rr = idx >> 3;
            const int c8 = (idx & 7) * 8;
            const long grow = boff + (long)(k0 + rr) * 3072;
            const int soff = rr * AT_STR + c8;
            cpa16(cvta_s(base + soff),               qh_g + grow + 1024 + c8);
            cpa16(cvta_s(base + AT_QSZ + soff),      ql_g + grow + 1024 + c8);
            cpa16(cvta_s(base + 2 * AT_QSZ + soff),  qh_g + grow + 2048 + c8);
            cpa16(cvta_s(base + 3 * AT_QSZ + soff),  ql_g + grow + 2048 + c8);
        }
    };

    issueKV(0, 0); CP_COMMIT();

    {
        const __nv_bfloat162 s2 = __floats2bfloat162_rn(0.125f, 0.125f);
        for (int idx = tid; idx < 512; idx += 128) {
            const int rr = idx >> 3;
            const int c8 = (idx & 7) * 8;
            const long grow = boff + (long)(n0 + rr) * 3072;
            uint4 vh = *(const uint4*)(qh_g + grow + c8);
            uint4 vl = *(const uint4*)(ql_g + grow + c8);
            __nv_bfloat162* ph = (__nv_bfloat162*)&vh;
            __nv_bfloat162* pl = (__nv_bfloat162*)&vl;
            #pragma unroll
            for (int e = 0; e < 4; e++) { ph[e] = __hmul2(ph[e], s2); pl[e] = __hmul2(pl[e], s2); }
            *(uint4*)(Qh + rr * AT_STR + c8) = vh;
            *(uint4*)(Ql + rr * AT_STR + c8) = vl;
        }
    }
    __syncthreads();

    uint32_t qh[4][4], ql[4][4];
    #pragma unroll
    for (int ks = 0; ks < 4; ks++) {
        const int row = warp * 16 + (lane & 15);
        const int col = ks * 16 + (lane >> 4) * 8;
        LDMX4(qh[ks], cvta_s(Qh + row * AT_STR + col));
        LDMX4(ql[ks], cvta_s(Ql + row * AT_STR + col));
    }

    float o[8][4];
    #pragma unroll
    for (int i = 0; i < 8; i++)
        #pragma unroll
        for (int e = 0; e < 4; e++) o[i][e] = 0.f;
    float mrow[2] = {-1e30f, -1e30f};
    float lrow[2] = {0.f, 0.f};

    int st = 0;
    for (int kt = 0; kt < 16; kt++) {
        const bool more = kt < 15;
        if (more) { issueKV(kt + 1, st ^ 1); CP_COMMIT(); }
        if (more) CP_WAIT(1); else CP_WAIT(0);
        __syncthreads();

        const __nv_bfloat16* Kh = sm + 2 * AT_QSZ + st * 4 * AT_QSZ;
        const __nv_bfloat16* Kl = Kh + AT_QSZ;
        const __nv_bfloat16* Vh = Kh + 2 * AT_QSZ;
        const __nv_bfloat16* Vl = Kh + 3 * AT_QSZ;

        // S = Q K^T over 64 keys; K fragments via x4 (BT mapping: fn-pairs)
        float s[8][4];
        #pragma unroll
        for (int fn = 0; fn < 8; fn++)
            #pragma unroll
            for (int e = 0; e < 4; e++) s[fn][e] = 0.f;

        #pragma unroll
        for (int ks = 0; ks < 4; ks++) {
            const int col = ks * 16 + ((lane >> 3) & 1) * 8;
            #pragma unroll
            for (int fp = 0; fp < 4; fp++) {
                uint32_t kh4[4], kl4[4];
                const int row = fp * 16 + (lane & 7) + ((lane >> 4) * 8);
                LDMX4(kh4, cvta_s(Kh + row * AT_STR + col));
                LDMX4(kl4, cvta_s(Kl + row * AT_STR + col));
                uint32_t kh2a[2] = { kh4[0], kh4[1] }, kh2b[2] = { kh4[2], kh4[3] };
                uint32_t kl2a[2] = { kl4[0], kl4[1] }, kl2b[2] = { kl4[2], kl4[3] };
                MMA16816(s[2 * fp],     qh[ks], kh2a);
                MMA16816(s[2 * fp],     qh[ks], kl2a);
                MMA16816(s[2 * fp],     ql[ks], kh2a);
                MMA16816(s[2 * fp + 1], qh[ks], kh2b);
                MMA16816(s[2 * fp + 1], qh[ks], kl2b);
                MMA16816(s[2 * fp + 1], ql[ks], kh2b);
            }
        }

        // online softmax (warp-local rows; quad lanes share a row)
        #pragma unroll
        for (int h2 = 0; h2 < 2; h2++) {
            float mx = mrow[h2];
            #pragma unroll
            for (int fn = 0; fn < 8; fn++)
                mx = fmaxf(mx, fmaxf(s[fn][2 * h2], s[fn][2 * h2 + 1]));
            mx = fmaxf(mx, __shfl_xor_sync(0xffffffffu, mx, 1));
            mx = fmaxf(mx, __shfl_xor_sync(0xffffffffu, mx, 2));
            const float alpha = __expf(mrow[h2] - mx);
            mrow[h2] = mx;
            float sum = 0.f;
            #pragma unroll
            for (int fn = 0; fn < 8; fn++) {
                float p0 = __expf(s[fn][2 * h2] - mx);
                float p1 = __expf(s[fn][2 * h2 + 1] - mx);
                s[fn][2 * h2] = p0; s[fn][2 * h2 + 1] = p1;
                sum += p0 + p1;
            }
            sum += __shfl_xor_sync(0xffffffffu, sum, 1);
            sum += __shfl_xor_sync(0xffffffffu, sum, 2);
            lrow[h2] = lrow[h2] * alpha + sum;
            #pragma unroll
            for (int fn = 0; fn < 8; fn++) {
                o[fn][2 * h2]     *= alpha;
                o[fn][2 * h2 + 1] *= alpha;
            }
        }

        // pack P (C-frag -> A-frag, bf16): 64 keys = 4 k16 fragments
        uint32_t pk[4][4];
        #pragma unroll
        for (int kf = 0; kf < 4; kf++) {
            pk[kf][0] = pack_bf2(s[2 * kf][0],     s[2 * kf][1]);
            pk[kf][1] = pack_bf2(s[2 * kf][2],     s[2 * kf][3]);
            pk[kf][2] = pack_bf2(s[2 * kf + 1][0], s[2 * kf + 1][1]);
            pk[kf][3] = pack_bf2(s[2 * kf + 1][2], s[2 * kf + 1][3]);
        }

        // O += P V; V fragments via x4 trans (NN mapping: fn-pairs)
        #pragma unroll
        for (int kf = 0; kf < 4; kf++) {
            const int row = kf * 16 + (lane & 7) + ((lane >> 3) & 1) * 8;
            #pragma unroll
            for (int fp = 0; fp < 4; fp++) {
                uint32_t vh4[4], vl4[4];
                const int col = fp * 16 + ((lane >> 4) * 8);
                LDMX4T(vh4, cvta_s(Vh + row * AT_STR + col));
                LDMX4T(vl4, cvta_s(Vl + row * AT_STR + col));
                uint32_t vh2a[2] = { vh4[0], vh4[1] }, vh2b[2] = { vh4[2], vh4[3] };
                uint32_t vl2a[2] = { vl4[0], vl4[1] }, vl2b[2] = { vl4[2], vl4[3] };
                MMA16816(o[2 * fp],     pk[kf], vh2a);
                MMA16816(o[2 * fp],     pk[kf], vl2a);
                MMA16816(o[2 * fp + 1], pk[kf], vh2b);
                MMA16816(o[2 * fp + 1], pk[kf], vl2b);
            }
        }
        __syncthreads();
        st ^= 1;
    }

    const float inv0 = 1.f / lrow[0];
    const float inv1 = 1.f / lrow[1];
    const int r0 = n0 + warp * 16 + (lane >> 2);
    const int cb = h * 64 + (lane & 3) * 2;
    #pragma unroll
    for (int fn = 0; fn < 8; fn++) {
        const int col = cb + fn * 8;
        float v0 = o[fn][0] * inv0, v1 = o[fn][1] * inv0;
        float v2 = o[fn][2] * inv1, v3 = o[fn][3] * inv1;
        __nv_bfloat16 h0, l0, h1, l1;
        split_bf16(v0, h0, l0); split_bf16(v1, h1, l1);
        *(__nv_bfloat162*)(oh + ((long)b * 1024 + r0) * 1024 + col) = __halves2bfloat162(h0, h1);
        *(__nv_bfloat162*)(ol + ((long)b * 1024 + r0) * 1024 + col) = __halves2bfloat162(l0, l1);
        split_bf16(v2, h0, l0); split_bf16(v3, h1, l1);
        *(__nv_bfloat162*)(oh + ((long)b * 1024 + r0 + 8) * 1024 + col) = __halves2bfloat162(h0, h1);
        *(__nv_bfloat162*)(ol + ((long)b * 1024 + r0 + 8) * 1024 + col) = __halves2bfloat162(l0, l1);
    }
}

// ---------------------------------------------------------------------------
// Launch
// ---------------------------------------------------------------------------
extern "C" void kernel_launch(void* const* d_in, const int* in_sizes, int n_in,
                              void* d_out, int out_size)
{
    (void)in_sizes; (void)n_in; (void)out_size;
    const float* x   = (const float*)d_in[0];
    const float* Wq0 = (const float*)d_in[1];
    const float* bq0 = (const float*)d_in[2];
    const float* Wq1 = (const float*)d_in[3];
    const float* bq1 = (const float*)d_in[4];
    const float* Wp0 = (const float*)d_in[5];
    const float* bp0 = (const float*)d_in[6];
    const float* Wp1 = (const float*)d_in[7];
    const float* bp1 = (const float*)d_in[8];
    float* out = (float*)d_out;

    __nv_bfloat16 *xh, *xl, *w0h, *w0l, *w1h, *w1l, *p0h, *p0l, *p1h, *p1l;
    __nv_bfloat16 *t1h, *t1l, *qh, *ql, *ah, *al, *t2h, *t2l;
    cudaGetSymbolAddress((void**)&xh,  g_xh);  cudaGetSymbolAddress((void**)&xl,  g_xl);
    cudaGetSymbolAddress((void**)&w0h, g_w0h); cudaGetSymbolAddress((void**)&w0l, g_w0l);
    cudaGetSymbolAddress((void**)&w1h, g_w1h); cudaGetSymbolAddress((void**)&w1l, g_w1l);
    cudaGetSymbolAddress((void**)&p0h, g_p0h); cudaGetSymbolAddress((void**)&p0l, g_p0l);
    cudaGetSymbolAddress((void**)&p1h, g_p1h); cudaGetSymbolAddress((void**)&p1l, g_p1l);
    cudaGetSymbolAddress((void**)&t1h, g_t1h); cudaGetSymbolAddress((void**)&t1l, g_t1l);
    cudaGetSymbolAddress((void**)&qh,  g_qh);  cudaGetSymbolAddress((void**)&ql,  g_ql);
    cudaGetSymbolAddress((void**)&ah,  g_ah);  cudaGetSymbolAddress((void**)&al,  g_al);
    cudaGetSymbolAddress((void**)&t2h, g_t2h); cudaGetSymbolAddress((void**)&t2l, g_t2l);

    const int smem_bt = 2 * ((2 * 128 * 40 + 2 * 128 * 40) * 2);   // 81920 B
    const int smem_nn = 2 * ((2 * 128 * 40 + 2 * 32 * 136) * 2);   // 75776 B
    cudaFuncSetAttribute(bgemm<true, true, true>,
                         cudaFuncAttributeMaxDynamicSharedMemorySize, smem_bt);
    cudaFuncSetAttribute(bgemm<true, true, false>,
                         cudaFuncAttributeMaxDynamicSharedMemorySize, smem_bt);
    cudaFuncSetAttribute(bgemm<false, false, true>,
                         cudaFuncAttributeMaxDynamicSharedMemorySize, smem_nn);

    const int attn_smem = 10 * AT_QSZ * 2;                         // 92160 B
    cudaFuncSetAttribute(attn_mma,
                         cudaFuncAttributeMaxDynamicSharedMemorySize, attn_smem);

    dim3 blk(256);
    const long P = 1024L * 1024;

    // 0) merged pre-split (x + all four weights), one launch
    presplit5<<<10240, blk>>>((const float4*)x, (const float4*)Wq0, (const float4*)Wq1,
                              (const float4*)Wp0, (const float4*)Wp1,
                              (__nv_bfloat162*)xh,  (__nv_bfloat162*)xl,
                              (__nv_bfloat162*)w0h, (__nv_bfloat162*)w0l,
                              (__nv_bfloat162*)w1h, (__nv_bfloat162*)w1l,
                              (__nv_bfloat162*)p0h, (__nv_bfloat162*)p0l,
                              (__nv_bfloat162*)p1h, (__nv_bfloat162*)p1l);

    // 1) qkv seq-linear (NN, 2-stage): t1[b] = Wq0 @ x[b] + bq0
    bgemm<false, false, true><<<dim3(8, 8, 4), blk, smem_nn>>>(
        w0h, w0l, xh, xl, bq0, nullptr, t1h, t1l, 1024, 1024, 1024, 0, P, P);

    // 2) qkv channel-linear (BT, 2-stage, 128-tile): qkv = t1 @ Wq1^T + bq1
    bgemm<true, true, true><<<dim3(24, 32, 1), blk, smem_bt>>>(
        t1h, t1l, w1h, w1l, bq1, nullptr, qh, ql, 4096, 3072, 1024, 0, 0, 0);

    // 3) flash attention (2 CTAs/SM, x4 ldmatrix)
    attn_mma<<<dim3(16, 16, 4), dim3(128), attn_smem>>>(qh, ql, ah, al);

    // 4) proj seq-linear (NN, 2-stage)
    bgemm<false, false, true><<<dim3(8, 8, 4), blk, smem_nn>>>(
        p0h, p0l, ah, al, bp0, nullptr, t2h, t2l, 1024, 1024, 1024, 0, P, P);

    // 5) proj channel-linear (BT, 2-stage, 128-tile) -> fp32 output
    bgemm<true, true, false><<<dim3(8, 32, 1), blk, smem_bt>>>(
        t2h, t2l, p1h, p1l, bp1, out, nullptr, nullptr, 4096, 1024, 1024, 0, 0, 0);
}